// round 5
// baseline (speedup 1.0000x reference)
#include <cuda_runtime.h>
#include <math.h>

#define BB 2
#define LL 128
#define DD 256
#define HH 256

// Output offsets (floats) in the packed d_out, reference tuple order.
#define OFF_ZQ2   0
#define OFF_W1P   65536
#define OFF_B1P   196608
#define OFF_W2P   197120
#define OFF_B2P   328192
#define OFF_MGW1  328704
#define OFF_MGB1  459776
#define OFF_MGW2  460288
#define OFF_MGB2  591360

// Scratch (device globals: allocation-free)
__device__ float g_q[BB*LL*DD];
__device__ float g_k[BB*LL*DD];
__device__ float g_v[BB*LL*DD];
__device__ float g_lr[BB*LL];
__device__ float g_logmom[BB*LL];
__device__ float g_logwd[BB*LL];
__device__ float g_cm[BB*LL];
__device__ float g_cd[BB*LL];
__device__ float g_momcum[BB*LL];
__device__ float g_wdcum[BB*LL];
__device__ float g_c[BB*LL];
__device__ float g_A[BB*LL*LL];
__device__ float g_X2[BB*LL*HH];
__device__ float g_gz1[BB*LL*HH];
__device__ float g_gz2[BB*LL*DD];
__device__ float g_sq[BB*LL*HH];
__device__ float g_p1[BB*LL*LL];   // p1[bl][m], zero-padded for m>l
__device__ float g_p2[BB*LL*LL];   // p2[bl][m], zero-padded for m>l
// Transposed fast weights
__device__ float g_W1T[BB*DD*HH];   // [b][d][h]  (W1 is [b][h][d])
__device__ float g_mW1T[BB*DD*HH];
__device__ float g_W2T[BB*HH*DD];   // [b][h][d]  (W2 is [b][d][h])
__device__ float g_mW2T[BB*HH*DD];

__device__ __forceinline__ float softplusf(float x){
    return fmaxf(x, 0.f) + log1pf(__expf(-fabsf(x)));
}

// ============================================================================
// KA: 4 weight transposes (blocks 0..511) + q/k/v proj + gates (blocks 512..703)
// ============================================================================
__global__ void KA(const float* __restrict__ x,
    const float* __restrict__ Wq, const float* __restrict__ bq,
    const float* __restrict__ Wk, const float* __restrict__ bk,
    const float* __restrict__ Wv, const float* __restrict__ bv,
    const float* __restrict__ Wlr, const float* __restrict__ blr,
    const float* __restrict__ Wm, const float* __restrict__ bm,
    const float* __restrict__ Wd, const float* __restrict__ bd,
    const float* __restrict__ W1, const float* __restrict__ mW1,
    const float* __restrict__ W2, const float* __restrict__ mW2,
    float lrshift)
{
    __shared__ float sbuf[1056];
    int idx = blockIdx.x, t = threadIdx.x;
    if (idx < 512){
        float (*tile)[33] = (float(*)[33])sbuf;
        int mat = idx >> 7, rem = idx & 127;
        int b = rem >> 6, tl = rem & 63;
        int by = tl >> 3, bx = tl & 7;
        const float* src = (mat==0)?W1:(mat==1)?mW1:(mat==2)?W2:mW2;
        float* dstp = ((mat==0)?g_W1T:(mat==1)?g_mW1T:(mat==2)?g_W2T:g_mW2T);
        src  += b*65536;
        dstp += b*65536;
        int tx = t & 31, ty = t >> 5;
        #pragma unroll
        for (int i = 0; i < 4; i++)
            tile[ty+8*i][tx] = src[(by*32+ty+8*i)*256 + bx*32+tx];
        __syncthreads();
        #pragma unroll
        for (int i = 0; i < 4; i++)
            dstp[(bx*32+ty+8*i)*256 + by*32+tx] = tile[tx][ty+8*i];
    } else {
        float (*xs)[256] = (float(*)[256])sbuf;
        int j = idx - 512;
        int mat3 = j >> 6, g = j & 63;
        int bl0 = 4*g;
        #pragma unroll
        for (int r = 0; r < 4; r++) xs[r][t] = x[(bl0+r)*DD + t];
        __syncthreads();
        if (mat3 == 0){
            int w = t >> 5, lane = t & 31;
            if (w < 4){
                float s0=0.f, s1=0.f, s2=0.f;
                #pragma unroll
                for (int i = lane; i < DD; i += 32){
                    float xv = xs[w][i];
                    s0 = fmaf(xv, Wlr[i], s0);
                    s1 = fmaf(xv, Wm[i],  s1);
                    s2 = fmaf(xv, Wd[i],  s2);
                }
                #pragma unroll
                for (int o = 16; o; o >>= 1){
                    s0 += __shfl_xor_sync(0xffffffffu, s0, o);
                    s1 += __shfl_xor_sync(0xffffffffu, s1, o);
                    s2 += __shfl_xor_sync(0xffffffffu, s2, o);
                }
                if (lane == 0){
                    int bl = bl0 + w;
                    g_lr[bl]     = softplusf(s0 + blr[0] + lrshift);
                    g_logmom[bl] = -softplusf(-(s1 + bm[0]));
                    g_logwd[bl]  = -softplusf(s2 + bd[0]);
                }
            }
        }
        const float* W    = (mat3==0)?Wq:(mat3==1)?Wk:Wv;
        const float* bias = (mat3==0)?bq:(mat3==1)?bk:bv;
        float* dst        = (mat3==0)?g_q:(mat3==1)?g_k:g_v;
        float a0=0.f, a1=0.f, a2=0.f, a3=0.f;
        #pragma unroll 8
        for (int i = 0; i < DD; i++){
            float w = W[i*DD + t];
            a0 = fmaf(xs[0][i], w, a0);
            a1 = fmaf(xs[1][i], w, a1);
            a2 = fmaf(xs[2][i], w, a2);
            a3 = fmaf(xs[3][i], w, a3);
        }
        float bb = bias[t];
        dst[(bl0+0)*DD + t] = a0 + bb;
        dst[(bl0+1)*DD + t] = a1 + bb;
        dst[(bl0+2)*DD + t] = a2 + bb;
        dst[(bl0+3)*DD + t] = a3 + bb;
    }
}

// ============================================================================
// KB: fast-weight fwd+grad (blocks 0..127, 2 rows each) + gate cumsums (128,129)
// ============================================================================
__global__ void KB(const float* __restrict__ W2,
                   const float* __restrict__ b1, const float* __restrict__ b2)
{
    __shared__ float sbuf[3*512];
    int idx = blockIdx.x, t = threadIdx.x;
    if (idx < 128){
        float (*krow)[256] = (float(*)[256])(sbuf);
        float (*x2s)[256]  = (float(*)[256])(sbuf + 512);
        float (*gz2s)[256] = (float(*)[256])(sbuf + 1024);
        int bl0 = 2*idx, b = bl0 >> 7;
        krow[0][t] = g_k[(bl0+0)*DD + t];
        krow[1][t] = g_k[(bl0+1)*DD + t];
        __syncthreads();
        const float* w1t = g_W1T + b*65536 + t;
        float bv1 = b1[b*HH + t];
        float z0=bv1, z1=bv1;
        #pragma unroll 8
        for (int i = 0; i < DD; i++){
            float w = w1t[i*HH];
            z0 = fmaf(krow[0][i], w, z0);
            z1 = fmaf(krow[1][i], w, z1);
        }
        float sg0 = __fdividef(1.f, 1.f + __expf(-z0));
        float sg1 = __fdividef(1.f, 1.f + __expf(-z1));
        float x20 = z0*sg0, x21 = z1*sg1;
        x2s[0][t]=x20; x2s[1][t]=x21;
        __syncthreads();
        const float* w2t = g_W2T + b*65536 + t;
        float bv2 = b2[b*DD + t];
        float y0=bv2, y1=bv2;
        #pragma unroll 8
        for (int h = 0; h < HH; h++){
            float w = w2t[h*DD];
            y0 = fmaf(x2s[0][h], w, y0);
            y1 = fmaf(x2s[1][h], w, y1);
        }
        float gA = y0 - g_v[(bl0+0)*DD + t];
        float gB = y1 - g_v[(bl0+1)*DD + t];
        gz2s[0][t]=gA; gz2s[1][t]=gB;
        g_gz2[(bl0+0)*DD+t]=gA; g_gz2[(bl0+1)*DD+t]=gB;
        __syncthreads();
        const float* w2c = W2 + b*65536 + t;
        float q0=0.f, q1=0.f;
        #pragma unroll 8
        for (int d = 0; d < DD; d++){
            float w = w2c[d*HH];
            q0 = fmaf(gz2s[0][d], w, q0);
            q1 = fmaf(gz2s[1][d], w, q1);
        }
        float sb0 = x20 + sg0*(1.f-x20);
        float sb1 = x21 + sg1*(1.f-x21);
        g_gz1[(bl0+0)*HH+t] = q0*sb0;  g_X2[(bl0+0)*HH+t] = x20;
        g_gz1[(bl0+1)*HH+t] = q1*sb1;  g_X2[(bl0+1)*HH+t] = x21;
    } else {
        int b = idx - 128;
        float* sm = sbuf; float* sd = sbuf + 128;
        if (t < LL){ sm[t] = g_logmom[b*LL + t]; sd[t] = g_logwd[b*LL + t]; }
        __syncthreads();
        if (t < LL){
            float cm = 0.f, cd = 0.f;
            for (int i = 0; i <= t; i++){ cm += sm[i]; cd += sd[i]; }
            g_cm[b*LL + t] = cm;
            g_cd[b*LL + t] = cd;
            g_momcum[b*LL + t] = __expf(cm);
            g_wdcum[b*LL + t]  = __expf(cd);
        }
    }
}

// ============================================================================
// KC: A = Dm@M (lower-tri LxL), c = Dm@mom_cum. grid (LL,BB), 128 threads.
// ============================================================================
__global__ void KC()
{
    int l = blockIdx.x, b = blockIdx.y;
    int m = threadIdx.x;
    __shared__ float cm[LL], cd[LL], red[LL];
    cm[m] = g_cm[b*LL + m];
    cd[m] = g_cd[b*LL + m];
    __syncthreads();
    float a = 0.f;
    if (m <= l){
        float base = cd[l] - cm[m];
        float s = 0.f;
        for (int j = m; j <= l; j++) s += __expf(base - cd[j] + cm[j]);
        a = s;
    }
    g_A[(b*LL + l)*LL + m] = a;
    red[m] = (m <= l) ? __expf(cd[l] - cd[m] + cm[m]) : 0.f;
    __syncthreads();
    for (int s = 64; s > 0; s >>= 1){
        if (m < s) red[m] += red[m + s];
        __syncthreads();
    }
    if (m == 0) g_c[b*LL + l] = red[0];
}

// ============================================================================
// KD1: p1 (blocks 0..255) + w1out (256..383) + w2out (384..511) + bout (512,513)
// ============================================================================
__global__ void KD1(const float* __restrict__ b1, const float* __restrict__ mb1,
                    const float* __restrict__ b2, const float* __restrict__ mb2,
                    const float* __restrict__ W1, const float* __restrict__ mW1,
                    const float* __restrict__ W2, const float* __restrict__ mW2,
                    float* __restrict__ out)
{
    __shared__ float sbuf[1024];
    int idx = blockIdx.x, t = threadIdx.x;
    const int rl = LL - 1;
    if (idx < 256){
        // ---- p1[bl][m] = A[l,m]*lr[m]*(1 + k[m]·q[l]), 0 for m>l ----
        float* qrow = sbuf;
        int bl = idx, b = bl >> 7, l = bl & 127;
        qrow[t] = g_q[bl*DD + t];
        __syncthreads();
        int w = t >> 5, lane = t & 31;
        for (int m = w; m < LL; m += 8){
            float val = 0.f;
            if (m <= l){
                const float* kr = g_k + (b*LL + m)*DD;
                float s = 0.f;
                #pragma unroll
                for (int i = lane; i < DD; i += 32) s = fmaf(kr[i], qrow[i], s);
                #pragma unroll
                for (int o = 16; o; o >>= 1) s += __shfl_xor_sync(0xffffffffu, s, o);
                val = g_A[bl*LL + m] * g_lr[b*LL + m] * (1.f + s);
            }
            if (lane == 0) g_p1[bl*LL + m] = val;
        }
    } else if (idx < 384){
        // ---- w1out: 4 h per block ----
        int jj = idx - 256;
        int b = jj >> 6, h0 = 4*(jj & 63);
        float (*ga)[128] = (float(*)[128])sbuf;
        float (*gm)[128] = (float(*)[128])(sbuf + 512);
        float cmL = g_cm[b*LL + rl];
        if (t < 128){
            int m = t;
            float lrm = g_lr[b*LL + m];
            float Av = g_A[(b*LL + rl)*LL + m]*lrm;
            float Mv = __expf(cmL - g_cm[b*LL + m])*lrm;
            float4 g4 = *(const float4*)(g_gz1 + (b*LL + m)*HH + h0);
            ga[0][m]=Av*g4.x; ga[1][m]=Av*g4.y; ga[2][m]=Av*g4.z; ga[3][m]=Av*g4.w;
            gm[0][m]=Mv*g4.x; gm[1][m]=Mv*g4.y; gm[2][m]=Mv*g4.z; gm[3][m]=Mv*g4.w;
        }
        __syncthreads();
        float s10=0.f,s11=0.f,s12=0.f,s13=0.f, s20=0.f,s21=0.f,s22=0.f,s23=0.f;
        const float* kp = g_k + b*LL*DD + t;
        #pragma unroll 4
        for (int m = 0; m < LL; m++){
            float kv = kp[m*DD];
            s10 = fmaf(ga[0][m], kv, s10); s20 = fmaf(gm[0][m], kv, s20);
            s11 = fmaf(ga[1][m], kv, s11); s21 = fmaf(gm[1][m], kv, s21);
            s12 = fmaf(ga[2][m], kv, s12); s22 = fmaf(gm[2][m], kv, s22);
            s13 = fmaf(ga[3][m], kv, s13); s23 = fmaf(gm[3][m], kv, s23);
        }
        float cL = g_c[b*LL+rl], wdL = g_wdcum[b*LL+rl], momL = g_momcum[b*LL+rl];
        #pragma unroll
        for (int r = 0; r < 4; r++){
            int h = h0 + r;
            float s1v = (r==0)?s10:(r==1)?s11:(r==2)?s12:s13;
            float s2v = (r==0)?s20:(r==1)?s21:(r==2)?s22:s23;
            float w1v  = W1[(b*HH + h)*DD + t];
            float mw1v = mW1[(b*HH + h)*DD + t];
            out[OFF_W1P  + (b*HH + h)*DD + t] = s1v - cL*mw1v + wdL*w1v;
            out[OFF_MGW1 + (b*HH + h)*DD + t] = s2v - momL*mw1v;
        }
    } else if (idx < 512){
        // ---- w2out: 4 d per block ----
        int jj = idx - 384;
        int b = jj >> 6, d0 = 4*(jj & 63);
        float (*ga)[128] = (float(*)[128])sbuf;
        float (*gm)[128] = (float(*)[128])(sbuf + 512);
        float cmL = g_cm[b*LL + rl];
        if (t < 128){
            int m = t;
            float lrm = g_lr[b*LL + m];
            float Av = g_A[(b*LL + rl)*LL + m]*lrm;
            float Mv = __expf(cmL - g_cm[b*LL + m])*lrm;
            float4 g4 = *(const float4*)(g_gz2 + (b*LL + m)*DD + d0);
            ga[0][m]=Av*g4.x; ga[1][m]=Av*g4.y; ga[2][m]=Av*g4.z; ga[3][m]=Av*g4.w;
            gm[0][m]=Mv*g4.x; gm[1][m]=Mv*g4.y; gm[2][m]=Mv*g4.z; gm[3][m]=Mv*g4.w;
        }
        __syncthreads();
        float s10=0.f,s11=0.f,s12=0.f,s13=0.f, s20=0.f,s21=0.f,s22=0.f,s23=0.f;
        const float* xp = g_X2 + b*LL*HH + t;
        #pragma unroll 4
        for (int m = 0; m < LL; m++){
            float xv = xp[m*HH];
            s10 = fmaf(ga[0][m], xv, s10); s20 = fmaf(gm[0][m], xv, s20);
            s11 = fmaf(ga[1][m], xv, s11); s21 = fmaf(gm[1][m], xv, s21);
            s12 = fmaf(ga[2][m], xv, s12); s22 = fmaf(gm[2][m], xv, s22);
            s13 = fmaf(ga[3][m], xv, s13); s23 = fmaf(gm[3][m], xv, s23);
        }
        float cL = g_c[b*LL+rl], wdL = g_wdcum[b*LL+rl], momL = g_momcum[b*LL+rl];
        #pragma unroll
        for (int r = 0; r < 4; r++){
            int d = d0 + r;
            float s1v = (r==0)?s10:(r==1)?s11:(r==2)?s12:s13;
            float s2v = (r==0)?s20:(r==1)?s21:(r==2)?s22:s23;
            float w2v  = W2[(b*DD + d)*HH + t];
            float mw2v = mW2[(b*DD + d)*HH + t];
            out[OFF_W2P  + (b*DD + d)*HH + t] = s1v - cL*mw2v + wdL*w2v;
            out[OFF_MGW2 + (b*DD + d)*HH + t] = s2v - momL*mw2v;
        }
    } else {
        // ---- bout: one block per batch ----
        int b = idx - 512;
        float* aw = sbuf; float* mw = sbuf + 128;
        if (t < 128){
            float lrm = g_lr[b*LL + t];
            aw[t] = g_A[(b*LL + rl)*LL + t]*lrm;
            mw[t] = __expf(g_cm[b*LL + rl] - g_cm[b*LL + t])*lrm;
        }
        __syncthreads();
        float cL = g_c[b*LL+rl], wdL = g_wdcum[b*LL+rl], momL = g_momcum[b*LL+rl];
        float s1=0.f, s2=0.f;
        const float* gz1p = g_gz1 + b*LL*HH + t;
        #pragma unroll 8
        for (int m = 0; m < LL; m++){
            float g = gz1p[m*HH];
            s1 = fmaf(aw[m], g, s1);
            s2 = fmaf(mw[m], g, s2);
        }
        out[OFF_B1P  + b*HH + t] = s1 - cL*mb1[b*HH + t] + wdL*b1[b*HH + t];
        out[OFF_MGB1 + b*HH + t] = s2 - momL*mb1[b*HH + t];
        float s3=0.f, s4=0.f;
        const float* gz2p = g_gz2 + b*LL*DD + t;
        #pragma unroll 8
        for (int m = 0; m < LL; m++){
            float g = gz2p[m*DD];
            s3 = fmaf(aw[m], g, s3);
            s4 = fmaf(mw[m], g, s4);
        }
        out[OFF_B2P  + b*DD + t] = s3 - cL*mb2[b*DD + t] + wdL*b2[b*DD + t];
        out[OFF_MGB2 + b*DD + t] = s4 - momL*mb2[b*DD + t];
    }
}

// ============================================================================
// KD2: zq1 phase-B, 2 rows per block, 128 blocks, 256 threads.
// ============================================================================
__global__ void KD2(const float* __restrict__ b1, const float* __restrict__ mb1)
{
    __shared__ float qrow[2][256];
    __shared__ float p1s[2][128];
    int idx = blockIdx.x, t = threadIdx.x;
    int bl0 = 2*idx, b = bl0 >> 7;
    qrow[0][t] = g_q[(bl0+0)*DD + t];
    qrow[1][t] = g_q[(bl0+1)*DD + t];
    ((float*)p1s)[t] = g_p1[bl0*LL + t];   // 256 = 2 rows x 128
    __syncthreads();
    float a0=0.f, a1=0.f;
    const float* gz = g_gz1 + b*LL*HH + t;
    #pragma unroll 8
    for (int m = 0; m < LL; m++){
        float gv = gz[m*HH];
        a0 = fmaf(p1s[0][m], gv, a0);
        a1 = fmaf(p1s[1][m], gv, a1);
    }
    const float* w1t  = g_W1T  + b*65536 + t;
    const float* mw1t = g_mW1T + b*65536 + t;
    float u0=0.f,u1=0.f, v0=0.f,v1=0.f;
    #pragma unroll 8
    for (int i = 0; i < DD; i++){
        float wv = w1t[i*HH], mv = mw1t[i*HH];
        float q0 = qrow[0][i], q1 = qrow[1][i];
        u0 = fmaf(q0, wv, u0); v0 = fmaf(q0, mv, v0);
        u1 = fmaf(q1, wv, u1); v1 = fmaf(q1, mv, v1);
    }
    float mb = mb1[b*HH + t], bbv = b1[b*HH + t];
    float z0 = a0 - g_c[bl0+0]*(v0 + mb) + g_wdcum[bl0+0]*(u0 + bbv);
    float z1 = a1 - g_c[bl0+1]*(v1 + mb) + g_wdcum[bl0+1]*(u1 + bbv);
    float s0 = __fdividef(1.f, 1.f + __expf(-z0));
    float s1 = __fdividef(1.f, 1.f + __expf(-z1));
    g_sq[(bl0+0)*HH + t] = z0*s0;
    g_sq[(bl0+1)*HH + t] = z1*s1;
}

// ============================================================================
// KE1: p2[bl][m] = A[l,m]*lr[m]*(1 + X2[m]·sq[l]), 256 blocks, 256 threads.
// ============================================================================
__global__ void KE1()
{
    __shared__ float sqrow[256];
    int bl = blockIdx.x, t = threadIdx.x;
    int b = bl >> 7, l = bl & 127;
    sqrow[t] = g_sq[bl*HH + t];
    __syncthreads();
    int w = t >> 5, lane = t & 31;
    for (int m = w; m < LL; m += 8){
        float val = 0.f;
        if (m <= l){
            const float* xr = g_X2 + (b*LL + m)*HH;
            float s = 0.f;
            #pragma unroll
            for (int i = lane; i < HH; i += 32) s = fmaf(xr[i], sqrow[i], s);
            #pragma unroll
            for (int o = 16; o; o >>= 1) s += __shfl_xor_sync(0xffffffffu, s, o);
            val = g_A[bl*LL + m] * g_lr[b*LL + m] * (1.f + s);
        }
        if (lane == 0) g_p2[bl*LL + m] = val;
    }
}

// ============================================================================
// KE2: zq2 phase-B, 2 rows per block, 128 blocks, 256 threads. Writes out.
// ============================================================================
__global__ void KE2(const float* __restrict__ b2, const float* __restrict__ mb2,
                    float* __restrict__ out)
{
    __shared__ float sqr[2][256];
    __shared__ float p2s[2][128];
    int idx = blockIdx.x, t = threadIdx.x;
    int bl0 = 2*idx, b = bl0 >> 7;
    sqr[0][t] = g_sq[(bl0+0)*HH + t];
    sqr[1][t] = g_sq[(bl0+1)*HH + t];
    ((float*)p2s)[t] = g_p2[bl0*LL + t];
    __syncthreads();
    float a0=0.f, a1=0.f;
    const float* gz = g_gz2 + b*LL*DD + t;
    #pragma unroll 8
    for (int m = 0; m < LL; m++){
        float gv = gz[m*DD];
        a0 = fmaf(p2s[0][m], gv, a0);
        a1 = fmaf(p2s[1][m], gv, a1);
    }
    const float* w2t  = g_W2T  + b*65536 + t;
    const float* mw2t = g_mW2T + b*65536 + t;
    float u0=0.f,u1=0.f, v0=0.f,v1=0.f;
    #pragma unroll 8
    for (int h = 0; h < HH; h++){
        float wv = w2t[h*DD], mv = mw2t[h*DD];
        float q0 = sqr[0][h], q1 = sqr[1][h];
        u0 = fmaf(q0, wv, u0); v0 = fmaf(q0, mv, v0);
        u1 = fmaf(q1, wv, u1); v1 = fmaf(q1, mv, v1);
    }
    float mb = mb2[b*DD + t], bbv = b2[b*DD + t];
    out[OFF_ZQ2 + (bl0+0)*DD + t] =
        a0 - g_c[bl0+0]*(v0 + mb) + g_wdcum[bl0+0]*(u0 + bbv);
    out[OFF_ZQ2 + (bl0+1)*DD + t] =
        a1 - g_c[bl0+1]*(v1 + mb) + g_wdcum[bl0+1]*(u1 + bbv);
}

extern "C" void kernel_launch(void* const* d_in, const int* in_sizes, int n_in,
                              void* d_out, int out_size)
{
    const float* x   = (const float*)d_in[0];
    const float* Wq  = (const float*)d_in[1];
    const float* bq  = (const float*)d_in[2];
    const float* Wk  = (const float*)d_in[3];
    const float* bk  = (const float*)d_in[4];
    const float* Wv  = (const float*)d_in[5];
    const float* bv  = (const float*)d_in[6];
    const float* Wlr = (const float*)d_in[7];
    const float* blr = (const float*)d_in[8];
    const float* Wm  = (const float*)d_in[9];
    const float* bm  = (const float*)d_in[10];
    const float* Wd  = (const float*)d_in[11];
    const float* bd  = (const float*)d_in[12];
    const float* W1  = (const float*)d_in[13];
    const float* b1  = (const float*)d_in[14];
    const float* W2  = (const float*)d_in[15];
    const float* b2  = (const float*)d_in[16];
    const float* mW1 = (const float*)d_in[17];
    const float* mb1 = (const float*)d_in[18];
    const float* mW2 = (const float*)d_in[19];
    const float* mb2 = (const float*)d_in[20];
    float* out = (float*)d_out;

    float lrshift = logf(expm1f(0.01f));   // LR_SHIFT

    KA<<<704, 256>>>(x, Wq, bq, Wk, bk, Wv, bv, Wlr, blr, Wm, bm, Wd, bd,
                     W1, mW1, W2, mW2, lrshift);
    KB<<<130, 256>>>(W2, b1, b2);
    KC<<<dim3(LL, BB), LL>>>();
    KD1<<<514, 256>>>(b1, mb1, b2, mb2, W1, mW1, W2, mW2, out);
    KD2<<<128, 256>>>(b1, mb1);
    KE1<<<256, 256>>>();
    KE2<<<128, 256>>>(b2, mb2, out);
}

// round 6
// speedup vs baseline: 1.4475x; 1.4475x over previous
#include <cuda_runtime.h>
#include <math.h>

#define BB 2
#define LL 128
#define DD 256
#define HH 256

// Output offsets (floats) in the packed d_out, reference tuple order.
#define OFF_ZQ2   0
#define OFF_W1P   65536
#define OFF_B1P   196608
#define OFF_W2P   197120
#define OFF_B2P   328192
#define OFF_MGW1  328704
#define OFF_MGB1  459776
#define OFF_MGW2  460288
#define OFF_MGB2  591360

// Scratch (device globals: allocation-free)
__device__ float g_q[BB*LL*DD];
__device__ float g_k[BB*LL*DD];
__device__ float g_v[BB*LL*DD];
__device__ float g_lr[BB*LL];
__device__ float g_cm[BB*LL];
__device__ float g_cd[BB*LL];
__device__ float g_momcum[BB*LL];
__device__ float g_wdcum[BB*LL];
__device__ float g_c[BB*LL];
__device__ float g_A[BB*LL*LL];
__device__ float g_X2[BB*LL*HH];
__device__ float g_gz1[BB*LL*HH];
__device__ float g_gz2[BB*LL*DD];
__device__ float g_sq[BB*LL*HH];
__device__ float g_p1[BB*LL*LL];
__device__ float g_p2[BB*LL*LL];
__device__ float g_W1T[BB*DD*HH];
__device__ float g_mW1T[BB*DD*HH];
__device__ float g_W2T[BB*HH*DD];
__device__ float g_mW2T[BB*HH*DD];

// Grid barrier state (monotonic generation; self-resetting counter)
__device__ unsigned g_cnt = 0;
__device__ unsigned g_gen = 0;

__device__ __forceinline__ void gsync(unsigned G){
    __syncthreads();
    if (threadIdx.x == 0){
        __threadfence();
        volatile unsigned* genp = &g_gen;
        unsigned gen = *genp;
        if (atomicAdd(&g_cnt, 1u) == G - 1u){
            atomicExch(&g_cnt, 0u);
            __threadfence();
            atomicAdd(&g_gen, 1u);
        } else {
            while (*genp == gen){ }
            __threadfence();
        }
    }
    __syncthreads();
}

__device__ __forceinline__ float softplusf(float x){
    return fmaxf(x, 0.f) + log1pf(__expf(-fabsf(x)));
}

__global__ __launch_bounds__(256, 4)
void MEGA(const float* __restrict__ x,
    const float* __restrict__ Wq, const float* __restrict__ bq,
    const float* __restrict__ Wk, const float* __restrict__ bk,
    const float* __restrict__ Wv, const float* __restrict__ bv,
    const float* __restrict__ Wlr, const float* __restrict__ blr,
    const float* __restrict__ Wm, const float* __restrict__ bm,
    const float* __restrict__ Wd, const float* __restrict__ bd,
    const float* __restrict__ W1, const float* __restrict__ b1,
    const float* __restrict__ W2, const float* __restrict__ b2,
    const float* __restrict__ mW1, const float* __restrict__ mb1,
    const float* __restrict__ mW2, const float* __restrict__ mb2,
    float* __restrict__ out, float lrshift)
{
    __shared__ float sbuf[1536];
    const unsigned G = gridDim.x;
    const int t = threadIdx.x;
    const int rl = LL - 1;

    // ========== Phase 0: transposes(0..511) + proj(512..703) + gates/scan(704,705)
    for (unsigned idx = blockIdx.x; idx < 706; idx += G){
        if (idx < 512){
            float (*tile)[33] = (float(*)[33])sbuf;
            int mat = idx >> 7, rem = idx & 127;
            int b = rem >> 6, tl = rem & 63;
            int by = tl >> 3, bx = tl & 7;
            const float* src = (mat==0)?W1:(mat==1)?mW1:(mat==2)?W2:mW2;
            float* dstp = ((mat==0)?g_W1T:(mat==1)?g_mW1T:(mat==2)?g_W2T:g_mW2T);
            src  += b*65536;
            dstp += b*65536;
            int tx = t & 31, ty = t >> 5;
            #pragma unroll
            for (int i = 0; i < 4; i++)
                tile[ty+8*i][tx] = src[(by*32+ty+8*i)*256 + bx*32+tx];
            __syncthreads();
            #pragma unroll
            for (int i = 0; i < 4; i++)
                dstp[(bx*32+ty+8*i)*256 + by*32+tx] = tile[tx][ty+8*i];
        } else if (idx < 704){
            float (*xs)[256] = (float(*)[256])sbuf;
            int j = idx - 512;
            int mat3 = j >> 6, g = j & 63;
            int bl0 = 4*g;
            #pragma unroll
            for (int r = 0; r < 4; r++) xs[r][t] = x[(bl0+r)*DD + t];
            __syncthreads();
            const float* W    = (mat3==0)?Wq:(mat3==1)?Wk:Wv;
            const float* bias = (mat3==0)?bq:(mat3==1)?bk:bv;
            float* dst        = (mat3==0)?g_q:(mat3==1)?g_k:g_v;
            float a0=0.f, a1=0.f, a2=0.f, a3=0.f;
            #pragma unroll 8
            for (int i = 0; i < DD; i++){
                float w = W[i*DD + t];
                a0 = fmaf(xs[0][i], w, a0);
                a1 = fmaf(xs[1][i], w, a1);
                a2 = fmaf(xs[2][i], w, a2);
                a3 = fmaf(xs[3][i], w, a3);
            }
            float bb = bias[t];
            dst[(bl0+0)*DD + t] = a0 + bb;
            dst[(bl0+1)*DD + t] = a1 + bb;
            dst[(bl0+2)*DD + t] = a2 + bb;
            dst[(bl0+3)*DD + t] = a3 + bb;
        } else {
            // gates + cumsums for batch b
            int b = idx - 704;
            float* slm = sbuf; float* sld = sbuf + 128;
            int w = t >> 5, lane = t & 31;
            for (int tk = w; tk < LL; tk += 8){
                const float* xr = x + (b*LL + tk)*DD;
                float s0=0.f, s1=0.f, s2=0.f;
                #pragma unroll
                for (int i = lane; i < DD; i += 32){
                    float xv = xr[i];
                    s0 = fmaf(xv, Wlr[i], s0);
                    s1 = fmaf(xv, Wm[i],  s1);
                    s2 = fmaf(xv, Wd[i],  s2);
                }
                #pragma unroll
                for (int o = 16; o; o >>= 1){
                    s0 += __shfl_xor_sync(0xffffffffu, s0, o);
                    s1 += __shfl_xor_sync(0xffffffffu, s1, o);
                    s2 += __shfl_xor_sync(0xffffffffu, s2, o);
                }
                if (lane == 0){
                    g_lr[b*LL + tk] = softplusf(s0 + blr[0] + lrshift);
                    slm[tk] = -softplusf(-(s1 + bm[0]));
                    sld[tk] = -softplusf(s2 + bd[0]);
                }
            }
            __syncthreads();
            if (t < LL){
                float cm = 0.f, cd = 0.f;
                for (int i = 0; i <= t; i++){ cm += slm[i]; cd += sld[i]; }
                g_cm[b*LL + t] = cm;
                g_cd[b*LL + t] = cd;
                g_momcum[b*LL + t] = __expf(cm);
                g_wdcum[b*LL + t]  = __expf(cd);
            }
        }
        __syncthreads();
    }
    gsync(G);

    // ========== Phase 1: A-matrix (0..255) + fwd (256..383)
    for (unsigned idx = blockIdx.x; idx < 384; idx += G){
        if (idx < 256){
            int bl = idx, b = bl >> 7, l = bl & 127;
            float* cm = sbuf; float* cd = sbuf + 128; float* red = sbuf + 256;
            if (t < 128){ cm[t] = g_cm[b*LL + t]; cd[t] = g_cd[b*LL + t]; }
            __syncthreads();
            if (t < 128){
                int m = t;
                float a = 0.f;
                if (m <= l){
                    float base = cd[l] - cm[m];
                    float s = 0.f;
                    for (int j = m; j <= l; j++) s += __expf(base - cd[j] + cm[j]);
                    a = s;
                }
                g_A[bl*LL + m] = a;
                red[m] = (m <= l) ? __expf(cd[l] - cd[m] + cm[m]) : 0.f;
            }
            __syncthreads();
            for (int s = 64; s > 0; s >>= 1){
                if (t < s) red[t] += red[t + s];
                __syncthreads();
            }
            if (t == 0) g_c[bl] = red[0];
        } else {
            float (*krow)[256] = (float(*)[256])(sbuf);
            float (*x2s)[256]  = (float(*)[256])(sbuf + 512);
            float (*gz2s)[256] = (float(*)[256])(sbuf + 1024);
            int bl0 = 2*(idx - 256), b = bl0 >> 7;
            krow[0][t] = g_k[(bl0+0)*DD + t];
            krow[1][t] = g_k[(bl0+1)*DD + t];
            __syncthreads();
            const float* w1t = g_W1T + b*65536 + t;
            float bv1 = b1[b*HH + t];
            float z0=bv1, z1=bv1;
            #pragma unroll 8
            for (int i = 0; i < DD; i++){
                float w = w1t[i*HH];
                z0 = fmaf(krow[0][i], w, z0);
                z1 = fmaf(krow[1][i], w, z1);
            }
            float sg0 = __fdividef(1.f, 1.f + __expf(-z0));
            float sg1 = __fdividef(1.f, 1.f + __expf(-z1));
            float x20 = z0*sg0, x21 = z1*sg1;
            x2s[0][t]=x20; x2s[1][t]=x21;
            __syncthreads();
            const float* w2t = g_W2T + b*65536 + t;
            float bv2 = b2[b*DD + t];
            float y0=bv2, y1=bv2;
            #pragma unroll 8
            for (int h = 0; h < HH; h++){
                float w = w2t[h*DD];
                y0 = fmaf(x2s[0][h], w, y0);
                y1 = fmaf(x2s[1][h], w, y1);
            }
            float gA = y0 - g_v[(bl0+0)*DD + t];
            float gB = y1 - g_v[(bl0+1)*DD + t];
            gz2s[0][t]=gA; gz2s[1][t]=gB;
            g_gz2[(bl0+0)*DD+t]=gA; g_gz2[(bl0+1)*DD+t]=gB;
            __syncthreads();
            const float* w2c = W2 + b*65536 + t;
            float q0=0.f, q1=0.f;
            #pragma unroll 8
            for (int d = 0; d < DD; d++){
                float w = w2c[d*HH];
                q0 = fmaf(gz2s[0][d], w, q0);
                q1 = fmaf(gz2s[1][d], w, q1);
            }
            float sb0 = x20 + sg0*(1.f-x20);
            float sb1 = x21 + sg1*(1.f-x21);
            g_gz1[(bl0+0)*HH+t] = q0*sb0;  g_X2[(bl0+0)*HH+t] = x20;
            g_gz1[(bl0+1)*HH+t] = q1*sb1;  g_X2[(bl0+1)*HH+t] = x21;
        }
        __syncthreads();
    }
    gsync(G);

    // ========== Phase 2: p1(0..255) + w1out(256..383) + w2out(384..511) + bout(512,513)
    for (unsigned idx = blockIdx.x; idx < 514; idx += G){
        if (idx < 256){
            float* qrow = sbuf;
            int bl = idx, b = bl >> 7, l = bl & 127;
            qrow[t] = g_q[bl*DD + t];
            __syncthreads();
            int w = t >> 5, lane = t & 31;
            for (int m = w; m < LL; m += 8){
                float val = 0.f;
                if (m <= l){
                    const float* kr = g_k + (b*LL + m)*DD;
                    float s = 0.f;
                    #pragma unroll
                    for (int i = lane; i < DD; i += 32) s = fmaf(kr[i], qrow[i], s);
                    #pragma unroll
                    for (int o = 16; o; o >>= 1) s += __shfl_xor_sync(0xffffffffu, s, o);
                    val = g_A[bl*LL + m] * g_lr[b*LL + m] * (1.f + s);
                }
                if (lane == 0) g_p1[bl*LL + m] = val;
            }
        } else if (idx < 384){
            int jj = idx - 256;
            int b = jj >> 6, h0 = 4*(jj & 63);
            float (*ga)[128] = (float(*)[128])sbuf;
            float (*gm)[128] = (float(*)[128])(sbuf + 512);
            float cmL = g_cm[b*LL + rl];
            if (t < 128){
                int m = t;
                float lrm = g_lr[b*LL + m];
                float Av = g_A[(b*LL + rl)*LL + m]*lrm;
                float Mv = __expf(cmL - g_cm[b*LL + m])*lrm;
                float4 g4 = *(const float4*)(g_gz1 + (b*LL + m)*HH + h0);
                ga[0][m]=Av*g4.x; ga[1][m]=Av*g4.y; ga[2][m]=Av*g4.z; ga[3][m]=Av*g4.w;
                gm[0][m]=Mv*g4.x; gm[1][m]=Mv*g4.y; gm[2][m]=Mv*g4.z; gm[3][m]=Mv*g4.w;
            }
            __syncthreads();
            float s10=0.f,s11=0.f,s12=0.f,s13=0.f, s20=0.f,s21=0.f,s22=0.f,s23=0.f;
            const float* kp = g_k + b*LL*DD + t;
            #pragma unroll 4
            for (int m = 0; m < LL; m++){
                float kv = kp[m*DD];
                s10 = fmaf(ga[0][m], kv, s10); s20 = fmaf(gm[0][m], kv, s20);
                s11 = fmaf(ga[1][m], kv, s11); s21 = fmaf(gm[1][m], kv, s21);
                s12 = fmaf(ga[2][m], kv, s12); s22 = fmaf(gm[2][m], kv, s22);
                s13 = fmaf(ga[3][m], kv, s13); s23 = fmaf(gm[3][m], kv, s23);
            }
            float cL = g_c[b*LL+rl], wdL = g_wdcum[b*LL+rl], momL = g_momcum[b*LL+rl];
            #pragma unroll
            for (int r = 0; r < 4; r++){
                int h = h0 + r;
                float s1v = (r==0)?s10:(r==1)?s11:(r==2)?s12:s13;
                float s2v = (r==0)?s20:(r==1)?s21:(r==2)?s22:s23;
                float w1v  = W1[(b*HH + h)*DD + t];
                float mw1v = mW1[(b*HH + h)*DD + t];
                out[OFF_W1P  + (b*HH + h)*DD + t] = s1v - cL*mw1v + wdL*w1v;
                out[OFF_MGW1 + (b*HH + h)*DD + t] = s2v - momL*mw1v;
            }
        } else if (idx < 512){
            int jj = idx - 384;
            int b = jj >> 6, d0 = 4*(jj & 63);
            float (*ga)[128] = (float(*)[128])sbuf;
            float (*gm)[128] = (float(*)[128])(sbuf + 512);
            float cmL = g_cm[b*LL + rl];
            if (t < 128){
                int m = t;
                float lrm = g_lr[b*LL + m];
                float Av = g_A[(b*LL + rl)*LL + m]*lrm;
                float Mv = __expf(cmL - g_cm[b*LL + m])*lrm;
                float4 g4 = *(const float4*)(g_gz2 + (b*LL + m)*DD + d0);
                ga[0][m]=Av*g4.x; ga[1][m]=Av*g4.y; ga[2][m]=Av*g4.z; ga[3][m]=Av*g4.w;
                gm[0][m]=Mv*g4.x; gm[1][m]=Mv*g4.y; gm[2][m]=Mv*g4.z; gm[3][m]=Mv*g4.w;
            }
            __syncthreads();
            float s10=0.f,s11=0.f,s12=0.f,s13=0.f, s20=0.f,s21=0.f,s22=0.f,s23=0.f;
            const float* xp = g_X2 + b*LL*HH + t;
            #pragma unroll 4
            for (int m = 0; m < LL; m++){
                float xv = xp[m*HH];
                s10 = fmaf(ga[0][m], xv, s10); s20 = fmaf(gm[0][m], xv, s20);
                s11 = fmaf(ga[1][m], xv, s11); s21 = fmaf(gm[1][m], xv, s21);
                s12 = fmaf(ga[2][m], xv, s12); s22 = fmaf(gm[2][m], xv, s22);
                s13 = fmaf(ga[3][m], xv, s13); s23 = fmaf(gm[3][m], xv, s23);
            }
            float cL = g_c[b*LL+rl], wdL = g_wdcum[b*LL+rl], momL = g_momcum[b*LL+rl];
            #pragma unroll
            for (int r = 0; r < 4; r++){
                int d = d0 + r;
                float s1v = (r==0)?s10:(r==1)?s11:(r==2)?s12:s13;
                float s2v = (r==0)?s20:(r==1)?s21:(r==2)?s22:s23;
                float w2v  = W2[(b*DD + d)*HH + t];
                float mw2v = mW2[(b*DD + d)*HH + t];
                out[OFF_W2P  + (b*DD + d)*HH + t] = s1v - cL*mw2v + wdL*w2v;
                out[OFF_MGW2 + (b*DD + d)*HH + t] = s2v - momL*mw2v;
            }
        } else {
            int b = idx - 512;
            float* aw = sbuf; float* mw = sbuf + 128;
            if (t < 128){
                float lrm = g_lr[b*LL + t];
                aw[t] = g_A[(b*LL + rl)*LL + t]*lrm;
                mw[t] = __expf(g_cm[b*LL + rl] - g_cm[b*LL + t])*lrm;
            }
            __syncthreads();
            float cL = g_c[b*LL+rl], wdL = g_wdcum[b*LL+rl], momL = g_momcum[b*LL+rl];
            float s1=0.f, s2=0.f;
            const float* gz1p = g_gz1 + b*LL*HH + t;
            #pragma unroll 8
            for (int m = 0; m < LL; m++){
                float g = gz1p[m*HH];
                s1 = fmaf(aw[m], g, s1);
                s2 = fmaf(mw[m], g, s2);
            }
            out[OFF_B1P  + b*HH + t] = s1 - cL*mb1[b*HH + t] + wdL*b1[b*HH + t];
            out[OFF_MGB1 + b*HH + t] = s2 - momL*mb1[b*HH + t];
            float s3=0.f, s4=0.f;
            const float* gz2p = g_gz2 + b*LL*DD + t;
            #pragma unroll 8
            for (int m = 0; m < LL; m++){
                float g = gz2p[m*DD];
                s3 = fmaf(aw[m], g, s3);
                s4 = fmaf(mw[m], g, s4);
            }
            out[OFF_B2P  + b*DD + t] = s3 - cL*mb2[b*DD + t] + wdL*b2[b*DD + t];
            out[OFF_MGB2 + b*DD + t] = s4 - momL*mb2[b*DD + t];
        }
        __syncthreads();
    }
    gsync(G);

    // ========== Phase 3: zq1 (0..127), 2 rows each
    for (unsigned idx = blockIdx.x; idx < 128; idx += G){
        float (*qrow)[256] = (float(*)[256])sbuf;
        float (*p1s)[128]  = (float(*)[128])(sbuf + 512);
        int bl0 = 2*idx, b = bl0 >> 7;
        qrow[0][t] = g_q[(bl0+0)*DD + t];
        qrow[1][t] = g_q[(bl0+1)*DD + t];
        ((float*)p1s)[t] = g_p1[bl0*LL + t];
        __syncthreads();
        float a0=0.f, a1=0.f;
        const float* gz = g_gz1 + b*LL*HH + t;
        #pragma unroll 8
        for (int m = 0; m < LL; m++){
            float gv = gz[m*HH];
            a0 = fmaf(p1s[0][m], gv, a0);
            a1 = fmaf(p1s[1][m], gv, a1);
        }
        const float* w1t  = g_W1T  + b*65536 + t;
        const float* mw1t = g_mW1T + b*65536 + t;
        float u0=0.f,u1=0.f, v0=0.f,v1=0.f;
        #pragma unroll 8
        for (int i = 0; i < DD; i++){
            float wv = w1t[i*HH], mv = mw1t[i*HH];
            float q0 = qrow[0][i], q1 = qrow[1][i];
            u0 = fmaf(q0, wv, u0); v0 = fmaf(q0, mv, v0);
            u1 = fmaf(q1, wv, u1); v1 = fmaf(q1, mv, v1);
        }
        float mb = mb1[b*HH + t], bbv = b1[b*HH + t];
        float z0 = a0 - g_c[bl0+0]*(v0 + mb) + g_wdcum[bl0+0]*(u0 + bbv);
        float z1 = a1 - g_c[bl0+1]*(v1 + mb) + g_wdcum[bl0+1]*(u1 + bbv);
        float s0 = __fdividef(1.f, 1.f + __expf(-z0));
        float s1 = __fdividef(1.f, 1.f + __expf(-z1));
        g_sq[(bl0+0)*HH + t] = z0*s0;
        g_sq[(bl0+1)*HH + t] = z1*s1;
        __syncthreads();
    }
    gsync(G);

    // ========== Phase 4: p2 (0..255)
    for (unsigned idx = blockIdx.x; idx < 256; idx += G){
        float* sqrow = sbuf;
        int bl = idx, b = bl >> 7, l = bl & 127;
        sqrow[t] = g_sq[bl*HH + t];
        __syncthreads();
        int w = t >> 5, lane = t & 31;
        for (int m = w; m < LL; m += 8){
            float val = 0.f;
            if (m <= l){
                const float* xr = g_X2 + (b*LL + m)*HH;
                float s = 0.f;
                #pragma unroll
                for (int i = lane; i < HH; i += 32) s = fmaf(xr[i], sqrow[i], s);
                #pragma unroll
                for (int o = 16; o; o >>= 1) s += __shfl_xor_sync(0xffffffffu, s, o);
                val = g_A[bl*LL + m] * g_lr[b*LL + m] * (1.f + s);
            }
            if (lane == 0) g_p2[bl*LL + m] = val;
        }
        __syncthreads();
    }
    gsync(G);

    // ========== Phase 5: zq2 (0..127), 2 rows each
    for (unsigned idx = blockIdx.x; idx < 128; idx += G){
        float (*sqr)[256] = (float(*)[256])sbuf;
        float (*p2s)[128] = (float(*)[128])(sbuf + 512);
        int bl0 = 2*idx, b = bl0 >> 7;
        sqr[0][t] = g_sq[(bl0+0)*HH + t];
        sqr[1][t] = g_sq[(bl0+1)*HH + t];
        ((float*)p2s)[t] = g_p2[bl0*LL + t];
        __syncthreads();
        float a0=0.f, a1=0.f;
        const float* gz = g_gz2 + b*LL*DD + t;
        #pragma unroll 8
        for (int m = 0; m < LL; m++){
            float gv = gz[m*DD];
            a0 = fmaf(p2s[0][m], gv, a0);
            a1 = fmaf(p2s[1][m], gv, a1);
        }
        const float* w2t  = g_W2T  + b*65536 + t;
        const float* mw2t = g_mW2T + b*65536 + t;
        float u0=0.f,u1=0.f, v0=0.f,v1=0.f;
        #pragma unroll 8
        for (int h = 0; h < HH; h++){
            float wv = w2t[h*DD], mv = mw2t[h*DD];
            float q0 = sqr[0][h], q1 = sqr[1][h];
            u0 = fmaf(q0, wv, u0); v0 = fmaf(q0, mv, v0);
            u1 = fmaf(q1, wv, u1); v1 = fmaf(q1, mv, v1);
        }
        float mb = mb2[b*DD + t], bbv = b2[b*DD + t];
        out[OFF_ZQ2 + (bl0+0)*DD + t] =
            a0 - g_c[bl0+0]*(v0 + mb) + g_wdcum[bl0+0]*(u0 + bbv);
        out[OFF_ZQ2 + (bl0+1)*DD + t] =
            a1 - g_c[bl0+1]*(v1 + mb) + g_wdcum[bl0+1]*(u1 + bbv);
        __syncthreads();
    }
}

extern "C" void kernel_launch(void* const* d_in, const int* in_sizes, int n_in,
                              void* d_out, int out_size)
{
    const float* x   = (const float*)d_in[0];
    const float* Wq  = (const float*)d_in[1];
    const float* bq  = (const float*)d_in[2];
    const float* Wk  = (const float*)d_in[3];
    const float* bk  = (const float*)d_in[4];
    const float* Wv  = (const float*)d_in[5];
    const float* bv  = (const float*)d_in[6];
    const float* Wlr = (const float*)d_in[7];
    const float* blr = (const float*)d_in[8];
    const float* Wm  = (const float*)d_in[9];
    const float* bm  = (const float*)d_in[10];
    const float* Wd  = (const float*)d_in[11];
    const float* bd  = (const float*)d_in[12];
    const float* W1  = (const float*)d_in[13];
    const float* b1  = (const float*)d_in[14];
    const float* W2  = (const float*)d_in[15];
    const float* b2  = (const float*)d_in[16];
    const float* mW1 = (const float*)d_in[17];
    const float* mb1 = (const float*)d_in[18];
    const float* mW2 = (const float*)d_in[19];
    const float* mb2 = (const float*)d_in[20];
    float* out = (float*)d_out;

    float lrshift = logf(expm1f(0.01f));   // LR_SHIFT

    // Size the persistent grid to guaranteed co-residency.
    int dev = 0;
    cudaGetDevice(&dev);
    int numSMs = 148;
    cudaDeviceGetAttribute(&numSMs, cudaDevAttrMultiProcessorCount, dev);
    int perSM = 1;
    cudaOccupancyMaxActiveBlocksPerMultiprocessor(&perSM, MEGA, 256, 0);
    if (perSM < 1) perSM = 1;
    long long Gl = (long long)numSMs * perSM;
    if (Gl > 706) Gl = 706;      // no more blocks than max items in any phase
    int G = (int)Gl;

    MEGA<<<G, 256>>>(x, Wq, bq, Wk, bk, Wv, bv, Wlr, blr, Wm, bm, Wd, bd,
                     W1, b1, W2, b2, mW1, mb1, mW2, mb2, out, lrshift);
}

// round 7
// speedup vs baseline: 2.5654x; 1.7723x over previous
#include <cuda_runtime.h>
#include <math.h>

#define BB 2
#define LL 128
#define DD 256
#define HH 256

#define OFF_ZQ2   0
#define OFF_W1P   65536
#define OFF_B1P   196608
#define OFF_W2P   197120
#define OFF_B2P   328192
#define OFF_MGW1  328704
#define OFF_MGB1  459776
#define OFF_MGW2  460288
#define OFF_MGB2  591360

// Scratch (device globals: allocation-free)
__device__ float g_q[BB*LL*DD];
__device__ float g_k[BB*LL*DD];
__device__ float g_v[BB*LL*DD];
__device__ float g_lr[BB*LL];
__device__ float g_cm[BB*LL];
__device__ float g_cd[BB*LL];
__device__ float g_momcum[BB*LL];
__device__ float g_wdcum[BB*LL];
__device__ float g_c[BB*LL];
__device__ float g_A[BB*LL*LL];
__device__ float g_X2[BB*LL*HH];
__device__ float g_gz1[BB*LL*HH];
__device__ float g_gz2[BB*LL*DD];
__device__ float g_W1T[BB*DD*HH];
__device__ float g_mW1T[BB*DD*HH];
__device__ float g_W2T[BB*HH*DD];
__device__ float g_mW2T[BB*HH*DD];

// Grid barrier state (monotonic generation; self-resetting counter)
__device__ unsigned g_cnt = 0;
__device__ unsigned g_gen = 0;

__device__ __forceinline__ void gsync(unsigned G){
    __syncthreads();
    if (threadIdx.x == 0){
        __threadfence();
        volatile unsigned* genp = &g_gen;
        unsigned gen = *genp;
        if (atomicAdd(&g_cnt, 1u) == G - 1u){
            atomicExch(&g_cnt, 0u);
            __threadfence();
            atomicAdd(&g_gen, 1u);
        } else {
            while (*genp == gen){ }
            __threadfence();
        }
    }
    __syncthreads();
}

__device__ __forceinline__ float softplusf(float x){
    return fmaxf(x, 0.f) + log1pf(__expf(-fabsf(x)));
}
__device__ __forceinline__ void fma4(float4& a, float4 w, float s){
    a.x = fmaf(w.x, s, a.x); a.y = fmaf(w.y, s, a.y);
    a.z = fmaf(w.z, s, a.z); a.w = fmaf(w.w, s, a.w);
}

__global__ __launch_bounds__(256, 4)
void MEGA(const float* __restrict__ x,
    const float* __restrict__ Wq, const float* __restrict__ bq,
    const float* __restrict__ Wk, const float* __restrict__ bk,
    const float* __restrict__ Wv, const float* __restrict__ bv,
    const float* __restrict__ Wlr, const float* __restrict__ blr,
    const float* __restrict__ Wm, const float* __restrict__ bm,
    const float* __restrict__ Wd, const float* __restrict__ bd,
    const float* __restrict__ W1, const float* __restrict__ b1,
    const float* __restrict__ W2, const float* __restrict__ b2,
    const float* __restrict__ mW1, const float* __restrict__ mb1,
    const float* __restrict__ mW2, const float* __restrict__ mb2,
    float* __restrict__ out, float lrshift)
{
    __shared__ __align__(16) float sbuf[3072];
    const unsigned G = gridDim.x;
    const int t = threadIdx.x;
    const int rl = LL - 1;
    const int g4 = t >> 6;          // i-group 0..3
    const int c4 = t & 63;          // column group (4 cols each)

    // ===== Phase 0: transposes(0..255, 2 tiles) + proj(256..447) + gates(448,449)
    for (unsigned idx = blockIdx.x; idx < 450; idx += G){
        if (idx < 256){
            float (*tile)[33] = (float(*)[33])sbuf;
            int mat = idx >> 6, rem = idx & 63;
            int b = rem >> 5, tp = (rem & 31)*2;
            const float* src = (mat==0)?W1:(mat==1)?mW1:(mat==2)?W2:mW2;
            float* dstp = ((mat==0)?g_W1T:(mat==1)?g_mW1T:(mat==2)?g_W2T:g_mW2T);
            src  += b*65536;
            dstp += b*65536;
            int tx = t & 31, ty = t >> 5;
            #pragma unroll
            for (int it = 0; it < 2; it++){
                int tl = tp + it;
                int by = tl >> 3, bx = tl & 7;
                #pragma unroll
                for (int i = 0; i < 4; i++)
                    tile[ty+8*i][tx] = src[(by*32+ty+8*i)*256 + bx*32+tx];
                __syncthreads();
                #pragma unroll
                for (int i = 0; i < 4; i++)
                    dstp[(bx*32+ty+8*i)*256 + by*32+tx] = tile[tx][ty+8*i];
                __syncthreads();
            }
        } else if (idx < 448){
            float (*xs)[256] = (float(*)[256])sbuf;       // 1024 floats
            float* red = sbuf + 1024;                     // 1024 floats
            int j = idx - 256;
            int mat3 = j >> 6, g = j & 63;
            int bl0 = 4*g;
            #pragma unroll
            for (int r = 0; r < 4; r++) xs[r][t] = x[(bl0+r)*DD + t];
            __syncthreads();
            const float* W    = (mat3==0)?Wq:(mat3==1)?Wk:Wv;
            const float* bias = (mat3==0)?bq:(mat3==1)?bk:bv;
            float* dst        = (mat3==0)?g_q:(mat3==1)?g_k:g_v;
            const float4* Wv4 = (const float4*)W;
            float4 a[4] = {{0,0,0,0},{0,0,0,0},{0,0,0,0},{0,0,0,0}};
            #pragma unroll 8
            for (int i = 64*g4; i < 64*g4+64; i++){
                float4 w = Wv4[i*64 + c4];
                fma4(a[0], w, xs[0][i]);
                fma4(a[1], w, xs[1][i]);
                fma4(a[2], w, xs[2][i]);
                fma4(a[3], w, xs[3][i]);
            }
            float bb = bias[t];
            #pragma unroll
            for (int r = 0; r < 4; r++){
                ((float4*)(red + g4*256))[c4] = a[r];
                __syncthreads();
                float y = red[t] + red[256+t] + red[512+t] + red[768+t];
                dst[(bl0+r)*DD + t] = y + bb;
                __syncthreads();
            }
        } else {
            int b = idx - 448;
            float* slm = sbuf; float* sld = sbuf + 128;
            int w = t >> 5, lane = t & 31;
            for (int tk = w; tk < LL; tk += 8){
                const float4* xr = (const float4*)(x + (b*LL + tk)*DD);
                float4 xa = xr[lane], xb = xr[32+lane];
                float4 wl0 = ((const float4*)Wlr)[lane], wl1 = ((const float4*)Wlr)[32+lane];
                float4 wm0 = ((const float4*)Wm)[lane],  wm1 = ((const float4*)Wm)[32+lane];
                float4 wd0 = ((const float4*)Wd)[lane],  wd1 = ((const float4*)Wd)[32+lane];
                float s0 = xa.x*wl0.x+xa.y*wl0.y+xa.z*wl0.z+xa.w*wl0.w
                         + xb.x*wl1.x+xb.y*wl1.y+xb.z*wl1.z+xb.w*wl1.w;
                float s1 = xa.x*wm0.x+xa.y*wm0.y+xa.z*wm0.z+xa.w*wm0.w
                         + xb.x*wm1.x+xb.y*wm1.y+xb.z*wm1.z+xb.w*wm1.w;
                float s2 = xa.x*wd0.x+xa.y*wd0.y+xa.z*wd0.z+xa.w*wd0.w
                         + xb.x*wd1.x+xb.y*wd1.y+xb.z*wd1.z+xb.w*wd1.w;
                #pragma unroll
                for (int o = 16; o; o >>= 1){
                    s0 += __shfl_xor_sync(0xffffffffu, s0, o);
                    s1 += __shfl_xor_sync(0xffffffffu, s1, o);
                    s2 += __shfl_xor_sync(0xffffffffu, s2, o);
                }
                if (lane == 0){
                    g_lr[b*LL + tk] = softplusf(s0 + blr[0] + lrshift);
                    slm[tk] = -softplusf(-(s1 + bm[0]));
                    sld[tk] = -softplusf(s2 + bd[0]);
                }
            }
            __syncthreads();
            if (t < LL){
                float cm = 0.f, cd = 0.f;
                for (int i = 0; i <= t; i++){ cm += slm[i]; cd += sld[i]; }
                g_cm[b*LL + t] = cm;
                g_cd[b*LL + t] = cd;
                g_momcum[b*LL + t] = __expf(cm);
                g_wdcum[b*LL + t]  = __expf(cd);
            }
        }
        __syncthreads();
    }
    gsync(G);

    // ===== Phase 1: A-matrix (0..255) + fwd (256..511, 1 row each)
    for (unsigned idx = blockIdx.x; idx < 512; idx += G){
        if (idx < 256){
            int bl = idx, b = bl >> 7, l = bl & 127;
            float* cm = sbuf; float* cd = sbuf + 128; float* red = sbuf + 256;
            if (t < 128){ cm[t] = g_cm[b*LL + t]; cd[t] = g_cd[b*LL + t]; }
            __syncthreads();
            if (t < 128){
                int m = t;
                float a = 0.f;
                if (m <= l){
                    float base = cd[l] - cm[m];
                    float s = 0.f;
                    for (int j = m; j <= l; j++) s += __expf(base - cd[j] + cm[j]);
                    a = s;
                }
                g_A[bl*LL + m] = a;
                red[m] = (m <= l) ? __expf(cd[l] - cd[m] + cm[m]) : 0.f;
            }
            __syncthreads();
            for (int s = 64; s > 0; s >>= 1){
                if (t < s) red[t] += red[t + s];
                __syncthreads();
            }
            if (t == 0) g_c[bl] = red[0];
        } else {
            int bl = idx - 256, b = bl >> 7;
            float* krow = sbuf;            // 256
            float* x2s  = sbuf + 256;      // 256
            float* gz2s = sbuf + 512;      // 256
            float* red  = sbuf + 768;      // 1024
            krow[t] = g_k[bl*DD + t];
            __syncthreads();
            // z1 = W1T^T k
            {
                const float4* M = (const float4*)(g_W1T + b*65536);
                float4 a = {0,0,0,0};
                #pragma unroll 8
                for (int i = 64*g4; i < 64*g4+64; i++)
                    fma4(a, M[i*64 + c4], krow[i]);
                ((float4*)(red + g4*256))[c4] = a;
            }
            __syncthreads();
            float z1 = red[t]+red[256+t]+red[512+t]+red[768+t] + b1[b*HH + t];
            float sig = __fdividef(1.f, 1.f + __expf(-z1));
            float x2 = z1*sig;
            x2s[t] = x2;
            __syncthreads();
            // z2 = W2T^T x2
            {
                const float4* M = (const float4*)(g_W2T + b*65536);
                float4 a = {0,0,0,0};
                #pragma unroll 8
                for (int i = 64*g4; i < 64*g4+64; i++)
                    fma4(a, M[i*64 + c4], x2s[i]);
                ((float4*)(red + g4*256))[c4] = a;
            }
            __syncthreads();
            float z2 = red[t]+red[256+t]+red[512+t]+red[768+t] + b2[b*DD + t];
            float gz2 = z2 - g_v[bl*DD + t];
            gz2s[t] = gz2;
            g_gz2[bl*DD + t] = gz2;
            __syncthreads();
            // gx2 = W2^T gz2 (original layout)
            {
                const float4* M = (const float4*)(W2 + b*65536);
                float4 a = {0,0,0,0};
                #pragma unroll 8
                for (int i = 64*g4; i < 64*g4+64; i++)
                    fma4(a, M[i*64 + c4], gz2s[i]);
                ((float4*)(red + g4*256))[c4] = a;
            }
            __syncthreads();
            float gx2 = red[t]+red[256+t]+red[512+t]+red[768+t];
            float sb = x2 + sig*(1.f - x2);
            g_gz1[bl*HH + t] = gx2*sb;
            g_X2[bl*HH + t]  = x2;
        }
        __syncthreads();
    }
    gsync(G);

    // ===== Phase 2: rowpipe(0..255) + w1out(256..383) + w2out(384..511) + bout(512,513)
    for (unsigned idx = blockIdx.x; idx < 514; idx += G){
        if (idx < 256){
            // --- per-row pipeline: p1 -> zq1 -> p2 -> zq2, all smem-resident ---
            int bl = idx, b = bl >> 7, l = bl & 127;
            float* qrow = sbuf;            // 256
            float* sqs  = sbuf + 256;      // 256
            float* pp   = sbuf + 512;      // 128
            float* red  = sbuf + 640;      // 1024
            int w = t >> 5, lane = t & 31;
            qrow[t] = g_q[bl*DD + t];
            __syncthreads();
            // p1[m] = A[l,m]*lr[m]*(1 + k[m]·q)
            for (int m = w; m < LL; m += 8){
                float val = 0.f;
                if (m <= l){
                    const float4* kr = (const float4*)(g_k + (b*LL + m)*DD);
                    const float4* q4 = (const float4*)qrow;
                    float4 ka = kr[lane], kb = kr[32+lane];
                    float4 qa = q4[lane], qb = q4[32+lane];
                    float s = ka.x*qa.x+ka.y*qa.y+ka.z*qa.z+ka.w*qa.w
                            + kb.x*qb.x+kb.y*qb.y+kb.z*qb.z+kb.w*qb.w;
                    #pragma unroll
                    for (int o = 16; o; o >>= 1) s += __shfl_xor_sync(0xffffffffu, s, o);
                    val = g_A[bl*LL + m]*g_lr[b*LL + m]*(1.f + s);
                }
                if (lane == 0) pp[m] = val;
            }
            __syncthreads();
            // acc = p1 · gz1[:,t]
            {
                const float4* Gz = (const float4*)(g_gz1 + b*LL*HH);
                float4 a = {0,0,0,0};
                #pragma unroll 8
                for (int m = 32*g4; m < 32*g4+32; m++)
                    fma4(a, Gz[m*64 + c4], pp[m]);
                ((float4*)(red + g4*256))[c4] = a;
            }
            __syncthreads();
            float acc = red[t]+red[256+t]+red[512+t]+red[768+t];
            __syncthreads();
            // w1q, mw1q
            float w1q, mw1q;
            {
                const float4* M  = (const float4*)(g_W1T  + b*65536);
                const float4* Mm = (const float4*)(g_mW1T + b*65536);
                float4 au = {0,0,0,0}, av = {0,0,0,0};
                #pragma unroll 4
                for (int i = 64*g4; i < 64*g4+64; i++){
                    float qv = qrow[i];
                    fma4(au, M[i*64 + c4], qv);
                    fma4(av, Mm[i*64 + c4], qv);
                }
                ((float4*)(red + g4*256))[c4] = au;
                __syncthreads();
                w1q = red[t]+red[256+t]+red[512+t]+red[768+t];
                __syncthreads();
                ((float4*)(red + g4*256))[c4] = av;
                __syncthreads();
                mw1q = red[t]+red[256+t]+red[512+t]+red[768+t];
            }
            float z = acc - g_c[bl]*(mw1q + mb1[b*HH + t]) + g_wdcum[bl]*(w1q + b1[b*HH + t]);
            float sg = __fdividef(1.f, 1.f + __expf(-z));
            sqs[t] = z*sg;
            __syncthreads();
            // p2[m] = A[l,m]*lr[m]*(1 + X2[m]·sq)
            for (int m = w; m < LL; m += 8){
                float val = 0.f;
                if (m <= l){
                    const float4* xr = (const float4*)(g_X2 + (b*LL + m)*HH);
                    const float4* s4 = (const float4*)sqs;
                    float4 xa = xr[lane], xb = xr[32+lane];
                    float4 sa = s4[lane], sb4 = s4[32+lane];
                    float s = xa.x*sa.x+xa.y*sa.y+xa.z*sa.z+xa.w*sa.w
                            + xb.x*sb4.x+xb.y*sb4.y+xb.z*sb4.z+xb.w*sb4.w;
                    #pragma unroll
                    for (int o = 16; o; o >>= 1) s += __shfl_xor_sync(0xffffffffu, s, o);
                    val = g_A[bl*LL + m]*g_lr[b*LL + m]*(1.f + s);
                }
                if (lane == 0) pp[m] = val;
            }
            __syncthreads();
            // acc2 = p2 · gz2[:,t]
            {
                const float4* Gz = (const float4*)(g_gz2 + b*LL*DD);
                float4 a = {0,0,0,0};
                #pragma unroll 8
                for (int m = 32*g4; m < 32*g4+32; m++)
                    fma4(a, Gz[m*64 + c4], pp[m]);
                ((float4*)(red + g4*256))[c4] = a;
            }
            __syncthreads();
            float acc2 = red[t]+red[256+t]+red[512+t]+red[768+t];
            __syncthreads();
            // w2s, mw2s
            float w2s, mw2s;
            {
                const float4* M  = (const float4*)(g_W2T  + b*65536);
                const float4* Mm = (const float4*)(g_mW2T + b*65536);
                float4 au = {0,0,0,0}, av = {0,0,0,0};
                #pragma unroll 4
                for (int i = 64*g4; i < 64*g4+64; i++){
                    float sv = sqs[i];
                    fma4(au, M[i*64 + c4], sv);
                    fma4(av, Mm[i*64 + c4], sv);
                }
                ((float4*)(red + g4*256))[c4] = au;
                __syncthreads();
                w2s = red[t]+red[256+t]+red[512+t]+red[768+t];
                __syncthreads();
                ((float4*)(red + g4*256))[c4] = av;
                __syncthreads();
                mw2s = red[t]+red[256+t]+red[512+t]+red[768+t];
            }
            out[OFF_ZQ2 + bl*DD + t] =
                acc2 - g_c[bl]*(mw2s + mb2[b*DD + t]) + g_wdcum[bl]*(w2s + b2[b*DD + t]);
        } else if (idx < 384){
            int jj = idx - 256;
            int b = jj >> 6, h0 = 4*(jj & 63);
            float (*ga)[128] = (float(*)[128])sbuf;
            float (*gm)[128] = (float(*)[128])(sbuf + 512);
            float cmL = g_cm[b*LL + rl];
            if (t < 128){
                int m = t;
                float lrm = g_lr[b*LL + m];
                float Av = g_A[(b*LL + rl)*LL + m]*lrm;
                float Mv = __expf(cmL - g_cm[b*LL + m])*lrm;
                float4 gg = *(const float4*)(g_gz1 + (b*LL + m)*HH + h0);
                ga[0][m]=Av*gg.x; ga[1][m]=Av*gg.y; ga[2][m]=Av*gg.z; ga[3][m]=Av*gg.w;
                gm[0][m]=Mv*gg.x; gm[1][m]=Mv*gg.y; gm[2][m]=Mv*gg.z; gm[3][m]=Mv*gg.w;
            }
            __syncthreads();
            float s10=0.f,s11=0.f,s12=0.f,s13=0.f, s20=0.f,s21=0.f,s22=0.f,s23=0.f;
            const float* kp = g_k + b*LL*DD + t;
            #pragma unroll 4
            for (int m = 0; m < LL; m++){
                float kv = kp[m*DD];
                s10 = fmaf(ga[0][m], kv, s10); s20 = fmaf(gm[0][m], kv, s20);
                s11 = fmaf(ga[1][m], kv, s11); s21 = fmaf(gm[1][m], kv, s21);
                s12 = fmaf(ga[2][m], kv, s12); s22 = fmaf(gm[2][m], kv, s22);
                s13 = fmaf(ga[3][m], kv, s13); s23 = fmaf(gm[3][m], kv, s23);
            }
            float cL = g_c[b*LL+rl], wdL = g_wdcum[b*LL+rl], momL = g_momcum[b*LL+rl];
            #pragma unroll
            for (int r = 0; r < 4; r++){
                int h = h0 + r;
                float s1v = (r==0)?s10:(r==1)?s11:(r==2)?s12:s13;
                float s2v = (r==0)?s20:(r==1)?s21:(r==2)?s22:s23;
                float w1v  = W1[(b*HH + h)*DD + t];
                float mw1v = mW1[(b*HH + h)*DD + t];
                out[OFF_W1P  + (b*HH + h)*DD + t] = s1v - cL*mw1v + wdL*w1v;
                out[OFF_MGW1 + (b*HH + h)*DD + t] = s2v - momL*mw1v;
            }
        } else if (idx < 512){
            int jj = idx - 384;
            int b = jj >> 6, d0 = 4*(jj & 63);
            float (*ga)[128] = (float(*)[128])sbuf;
            float (*gm)[128] = (float(*)[128])(sbuf + 512);
            float cmL = g_cm[b*LL + rl];
            if (t < 128){
                int m = t;
                float lrm = g_lr[b*LL + m];
                float Av = g_A[(b*LL + rl)*LL + m]*lrm;
                float Mv = __expf(cmL - g_cm[b*LL + m])*lrm;
                float4 gg = *(const float4*)(g_gz2 + (b*LL + m)*DD + d0);
                ga[0][m]=Av*gg.x; ga[1][m]=Av*gg.y; ga[2][m]=Av*gg.z; ga[3][m]=Av*gg.w;
                gm[0][m]=Mv*gg.x; gm[1][m]=Mv*gg.y; gm[2][m]=Mv*gg.z; gm[3][m]=Mv*gg.w;
            }
            __syncthreads();
            float s10=0.f,s11=0.f,s12=0.f,s13=0.f, s20=0.f,s21=0.f,s22=0.f,s23=0.f;
            const float* xp = g_X2 + b*LL*HH + t;
            #pragma unroll 4
            for (int m = 0; m < LL; m++){
                float xv = xp[m*DD];
                s10 = fmaf(ga[0][m], xv, s10); s20 = fmaf(gm[0][m], xv, s20);
                s11 = fmaf(ga[1][m], xv, s11); s21 = fmaf(gm[1][m], xv, s21);
                s12 = fmaf(ga[2][m], xv, s12); s22 = fmaf(gm[2][m], xv, s22);
                s13 = fmaf(ga[3][m], xv, s13); s23 = fmaf(gm[3][m], xv, s23);
            }
            float cL = g_c[b*LL+rl], wdL = g_wdcum[b*LL+rl], momL = g_momcum[b*LL+rl];
            #pragma unroll
            for (int r = 0; r < 4; r++){
                int d = d0 + r;
                float s1v = (r==0)?s10:(r==1)?s11:(r==2)?s12:s13;
                float s2v = (r==0)?s20:(r==1)?s21:(r==2)?s22:s23;
                float w2v  = W2[(b*DD + d)*HH + t];
                float mw2v = mW2[(b*DD + d)*HH + t];
                out[OFF_W2P  + (b*DD + d)*HH + t] = s1v - cL*mw2v + wdL*w2v;
                out[OFF_MGW2 + (b*DD + d)*HH + t] = s2v - momL*mw2v;
            }
        } else {
            int b = idx - 512;
            float* aw = sbuf; float* mw = sbuf + 128;
            if (t < 128){
                float lrm = g_lr[b*LL + t];
                aw[t] = g_A[(b*LL + rl)*LL + t]*lrm;
                mw[t] = __expf(g_cm[b*LL + rl] - g_cm[b*LL + t])*lrm;
            }
            __syncthreads();
            float cL = g_c[b*LL+rl], wdL = g_wdcum[b*LL+rl], momL = g_momcum[b*LL+rl];
            float s1=0.f, s2=0.f;
            const float* gz1p = g_gz1 + b*LL*HH + t;
            #pragma unroll 8
            for (int m = 0; m < LL; m++){
                float g = gz1p[m*HH];
                s1 = fmaf(aw[m], g, s1);
                s2 = fmaf(mw[m], g, s2);
            }
            out[OFF_B1P  + b*HH + t] = s1 - cL*mb1[b*HH + t] + wdL*b1[b*HH + t];
            out[OFF_MGB1 + b*HH + t] = s2 - momL*mb1[b*HH + t];
            float s3=0.f, s4=0.f;
            const float* gz2p = g_gz2 + b*LL*DD + t;
            #pragma unroll 8
            for (int m = 0; m < LL; m++){
                float g = gz2p[m*DD];
                s3 = fmaf(aw[m], g, s3);
                s4 = fmaf(mw[m], g, s4);
            }
            out[OFF_B2P  + b*DD + t] = s3 - cL*mb2[b*DD + t] + wdL*b2[b*DD + t];
            out[OFF_MGB2 + b*DD + t] = s4 - momL*mb2[b*DD + t];
        }
        __syncthreads();
    }
}

extern "C" void kernel_launch(void* const* d_in, const int* in_sizes, int n_in,
                              void* d_out, int out_size)
{
    const float* x   = (const float*)d_in[0];
    const float* Wq  = (const float*)d_in[1];
    const float* bq  = (const float*)d_in[2];
    const float* Wk  = (const float*)d_in[3];
    const float* bk  = (const float*)d_in[4];
    const float* Wv  = (const float*)d_in[5];
    const float* bv  = (const float*)d_in[6];
    const float* Wlr = (const float*)d_in[7];
    const float* blr = (const float*)d_in[8];
    const float* Wm  = (const float*)d_in[9];
    const float* bm  = (const float*)d_in[10];
    const float* Wd  = (const float*)d_in[11];
    const float* bd  = (const float*)d_in[12];
    const float* W1  = (const float*)d_in[13];
    const float* b1  = (const float*)d_in[14];
    const float* W2  = (const float*)d_in[15];
    const float* b2  = (const float*)d_in[16];
    const float* mW1 = (const float*)d_in[17];
    const float* mb1 = (const float*)d_in[18];
    const float* mW2 = (const float*)d_in[19];
    const float* mb2 = (const float*)d_in[20];
    float* out = (float*)d_out;

    float lrshift = logf(expm1f(0.01f));   // LR_SHIFT

    int dev = 0;
    cudaGetDevice(&dev);
    int numSMs = 148;
    cudaDeviceGetAttribute(&numSMs, cudaDevAttrMultiProcessorCount, dev);
    int perSM = 1;
    cudaOccupancyMaxActiveBlocksPerMultiprocessor(&perSM, MEGA, 256, 0);
    if (perSM < 1) perSM = 1;
    long long Gl = (long long)numSMs * perSM;
    if (Gl > 514) Gl = 514;    // largest phase item count
    int G = (int)Gl;

    MEGA<<<G, 256>>>(x, Wq, bq, Wk, bk, Wv, bv, Wlr, blr, Wm, bm, Wd, bd,
                     W1, b1, W2, b2, mW1, mb1, mW2, mb2, out, lrshift);
}